// round 13
// baseline (speedup 1.0000x reference)
#include <cuda_runtime.h>
#include <stdint.h>

#define KE_HALF 7.199822675975274f   /* KE/2 */
#define LOG2E   1.4426950408889634f
#define MAX_NODES 131072
#define ZSCALE   2048.0f
#define NTHREADS 256
#define CTAS_PER_SM 5

// 2B per node: qz = round(z * 2048). 195KB -> entire table is L1-resident.
__device__ uint16_t g_ztab[MAX_NODES];
__device__ float    g_par[12];  // [0..3]=-a_k*log2e, [4..7]=c_k norm, [8]=p, [9]=d*2^(-11p)

__device__ __forceinline__ float softplus_f(float x) {
    return fmaxf(x, 0.0f) + log1pf(__expf(-fabsf(x)));
}
__device__ __forceinline__ float ex2f(float x) {
    float y; asm("ex2.approx.ftz.f32 %0, %1;" : "=f"(y) : "f"(x)); return y;
}
__device__ __forceinline__ float lg2f(float x) {
    float y; asm("lg2.approx.ftz.f32 %0, %1;" : "=f"(y) : "f"(x)); return y;
}

// Streaming loads: evict-first so they don't displace the node table in L1.
__device__ __forceinline__ float4 ldcs4(const float4* p) {
    float4 v;
    asm("ld.global.cs.v4.f32 {%0,%1,%2,%3}, [%4];"
        : "=f"(v.x), "=f"(v.y), "=f"(v.z), "=f"(v.w) : "l"(p));
    return v;
}
__device__ __forceinline__ int4 ldcs4i(const int4* p) {
    int4 v;
    asm("ld.global.cs.v4.b32 {%0,%1,%2,%3}, [%4];"
        : "=r"(v.x), "=r"(v.y), "=r"(v.z), "=r"(v.w) : "l"(p));
    return v;
}

__device__ __forceinline__ void load_quad(int base, int E,
                                          const float* cut, const float* len,
                                          const int* snd, const int* rcv,
                                          float4& Lv, float4& Cv, int4& Sv, int4& Rv) {
    if (base + 3 < E) {
        Lv = ldcs4((const float4*)(len + base));
        Cv = ldcs4((const float4*)(cut + base));
        Sv = ldcs4i((const int4*)(snd + base));
        Rv = ldcs4i((const int4*)(rcv + base));
    } else {
        float* lp = &Lv.x; float* cp = &Cv.x; int* sp = &Sv.x; int* rp = &Rv.x;
        for (int k = 0; k < 4; k++) {
            int e = base + k;
            lp[k] = (e < E) ? len[e] : 2.0f;   // L >= 1.5 -> w == 0 -> no-op
            cp[k] = (e < E) ? cut[e] : 0.0f;
            sp[k] = (e < E) ? snd[e] : 0;
            rp[k] = (e < E) ? rcv[e] : 0;
        }
    }
}

// Fused: zero output + per-node 16-bit quantization + (thread 0) param derivation.
__global__ void node_kernel(const float* __restrict__ z,
                            const float* __restrict__ p_raw,
                            const float* __restrict__ d_raw,
                            const float* __restrict__ a1, const float* __restrict__ a2,
                            const float* __restrict__ a3, const float* __restrict__ a4,
                            const float* __restrict__ c1, const float* __restrict__ c2,
                            const float* __restrict__ c3, const float* __restrict__ c4,
                            float* __restrict__ out, int n, int n_out) {
    int i = blockIdx.x * blockDim.x + threadIdx.x;
    if (i == 0) {
        float A1 = softplus_f(a1[0]), A2 = softplus_f(a2[0]);
        float A3 = softplus_f(a3[0]), A4 = softplus_f(a4[0]);
        float C1 = softplus_f(c1[0]), C2 = softplus_f(c2[0]);
        float C3 = softplus_f(c3[0]), C4 = softplus_f(c4[0]);
        float s = 1.0f / (C1 + C2 + C3 + C4);
        float P = softplus_f(p_raw[0]);
        float D = softplus_f(d_raw[0]);
        g_par[0] = -A1 * LOG2E; g_par[1] = -A2 * LOG2E;
        g_par[2] = -A3 * LOG2E; g_par[3] = -A4 * LOG2E;
        g_par[4] = C1 * s; g_par[5] = C2 * s; g_par[6] = C3 * s; g_par[7] = C4 * s;
        g_par[8] = P;
        g_par[9] = D * ex2f(-11.0f * P);   // z^p*d = DS * 2^(p*lg2(qz)), qz = z*2^11
    }
    if (i < n_out) out[i] = 0.0f;
    if (i < n) {
        unsigned q = __float2uint_rn(z[i] * ZSCALE);
        g_ztab[i] = (uint16_t)(q > 65535u ? 65535u : q);
    }
}

__global__ void __launch_bounds__(NTHREADS, CTAS_PER_SM)
edge_kernel(const float* __restrict__ cut, const float* __restrict__ len,
            const int* __restrict__ snd, const int* __restrict__ rcv,
            float* __restrict__ out, int E) {
    const float b1 = g_par[0], b2 = g_par[1], b3 = g_par[2], b4 = g_par[3];
    const float c1 = g_par[4], c2 = g_par[5], c3 = g_par[6], c4 = g_par[7];
    const float P  = g_par[8], DS = g_par[9];

    const int nq = (E + 3) >> 2;
    const int stride = gridDim.x * NTHREADS;
    int q = blockIdx.x * NTHREADS + threadIdx.x;
    if (q >= nq) return;

    // Software pipeline: streaming loads for quad i+stride issued before
    // the gathers/math of quad i, hiding DRAM latency behind body work.
    float4 Lv, Cv; int4 Sv, Rv;
    load_quad(q << 2, E, cut, len, snd, rcv, Lv, Cv, Sv, Rv);

    while (true) {
        int qn = q + stride;
        bool have_next = qn < nq;
        float4 Ln, Cn; int4 Sn, Rn;
        if (have_next) load_quad(qn << 2, E, cut, len, snd, rcv, Ln, Cn, Sn, Rn);

        const float* lp = &Lv.x; const float* cp = &Cv.x;
        const int* sp = &Sv.x; const int* rp = &Rv.x;

        // ── Phase A: predicated 2B gathers back-to-back (table L1-resident).
        unsigned QS[4], QR[4];
        bool act[4];
#pragma unroll
        for (int k = 0; k < 4; k++) {
            act[k] = lp[k] < 1.5f;             // w == 0 exactly for L >= 1.5
            QS[k] = 2048; QR[k] = 2048;
            if (act[k]) {
                QS[k] = (unsigned)g_ztab[sp[k]];
                QR[k] = (unsigned)g_ztab[rp[k]];
            }
        }

        // ── Phase B: math + fire-and-forget atomics.
#pragma unroll
        for (int k = 0; k < 4; k++) {
            if (!act[k]) continue;
            float L = lp[k];
            float cc = L * (1.0f / 1.5f);

            // w*x*0.5 = KE_HALF*cut*zi*zj / ((1 + 2^fl) * L)
            float om = 1.0f - cc;
            float fl = __fdividef((cc + cc - 1.0f) * LOG2E, cc * om);
            float ef = ex2f(fl);
            float D  = (1.0f + ef) * fmaxf(L, 1e-6f);

            float zps = ex2f(P * lg2f((float)QS[k]));
            float zpr = ex2f(P * lg2f((float)QR[k]));
            float zz  = (float)(QS[k] * QR[k]);         // < 2^32

            float num = (KE_HALF / (ZSCALE * ZSCALE)) * cp[k] * zz;
            float t   = L * DS * (zps + zpr);           // rzd
            float y = c1 * ex2f(b1 * t) + c2 * ex2f(b2 * t)
                    + c3 * ex2f(b3 * t) + c4 * ex2f(b4 * t);

            atomicAdd(out + rp[k], __fdividef(num * y, D));
        }

        if (!have_next) break;
        q = qn;
        Lv = Ln; Cv = Cn; Sv = Sn; Rv = Rn;
    }
}

extern "C" void kernel_launch(void* const* d_in, const int* in_sizes, int n_in,
                              void* d_out, int out_size) {
    const float* z   = (const float*)d_in[0];
    const float* cut = (const float*)d_in[1];
    const int*   snd = (const int*)  d_in[2];
    const int*   rcv = (const int*)  d_in[3];
    const float* len = (const float*)d_in[4];

    int pb = n_in - 10;
    const float* a1 = (const float*)d_in[pb + 0];
    const float* a2 = (const float*)d_in[pb + 1];
    const float* a3 = (const float*)d_in[pb + 2];
    const float* a4 = (const float*)d_in[pb + 3];
    const float* c1 = (const float*)d_in[pb + 4];
    const float* c2 = (const float*)d_in[pb + 5];
    const float* c3 = (const float*)d_in[pb + 6];
    const float* c4 = (const float*)d_in[pb + 7];
    const float* pr = (const float*)d_in[pb + 8];
    const float* dr = (const float*)d_in[pb + 9];

    int N = in_sizes[0];
    int E = in_sizes[2];
    if (N > MAX_NODES) N = MAX_NODES;

    float* out = (float*)d_out;

    int cover = (N > out_size) ? N : out_size;
    node_kernel<<<(cover + 255) / 256, 256>>>(z, pr, dr, a1, a2, a3, a4,
                                              c1, c2, c3, c4, out, N, out_size);

    static int nsm = 0;
    if (nsm == 0) {
        cudaDeviceGetAttribute(&nsm, cudaDevAttrMultiProcessorCount, 0);
        if (nsm <= 0) nsm = 148;
    }
    // Persistent-ish grid: CTAS_PER_SM resident CTAs per SM, ~8 iterations each.
    int grid = nsm * CTAS_PER_SM;
    edge_kernel<<<grid, NTHREADS>>>(cut, len, snd, rcv, out, E);
}

// round 14
// speedup vs baseline: 1.1750x; 1.1750x over previous
#include <cuda_runtime.h>
#include <stdint.h>

#define KE_HALF 7.199822675975274f   /* KE/2 */
#define LOG2E   1.4426950408889634f
#define MAX_NODES 131072
#define ZSCALE   2048.0f
#define YLUT_N   1024
#define YLUT_TMAX 16.0f
#define GLUT_N   512                 /* over L in [0.5, 1.5) */
#define LUT_TOTAL (YLUT_N + GLUT_N)
#define LUT_BYTES (LUT_TOTAL * 8)    /* 12288 */
#define SMEM_CAP_NODES 104000        /* 208000B table + 12288B LUT = 215.1KB */
#define NTHREADS 1024

// 2B per node: qz = round(z * 2048).
__device__ uint16_t g_ztab[MAX_NODES];
// Prebuilt LUTs: [0,1024) y(t) over [0,16]; [1024,1536) w(L)/L over [0.5,1.5).
__device__ float2   g_lut[LUT_TOTAL];
__device__ float    g_par[4];        // [0]=p, [1]=d*2^(-11p)

__device__ __forceinline__ float softplus_f(float x) {
    return fmaxf(x, 0.0f) + log1pf(__expf(-fabsf(x)));
}
__device__ __forceinline__ float ex2f(float x) {
    float y; asm("ex2.approx.ftz.f32 %0, %1;" : "=f"(y) : "f"(x)); return y;
}
__device__ __forceinline__ float lg2f(float x) {
    float y; asm("lg2.approx.ftz.f32 %0, %1;" : "=f"(y) : "f"(x)); return y;
}

__device__ __forceinline__ float4 ldcs4(const float4* p) {
    float4 v;
    asm("ld.global.cs.v4.f32 {%0,%1,%2,%3}, [%4];"
        : "=f"(v.x), "=f"(v.y), "=f"(v.z), "=f"(v.w) : "l"(p));
    return v;
}
__device__ __forceinline__ int4 ldcs4i(const int4* p) {
    int4 v;
    asm("ld.global.cs.v4.b32 {%0,%1,%2,%3}, [%4];"
        : "=r"(v.x), "=r"(v.y), "=r"(v.z), "=r"(v.w) : "l"(p));
    return v;
}

__device__ __forceinline__ float switch_w(float L) {
    float c = L * (1.0f / 1.5f);
    if (c >= 1.0f) return 0.0f;
    float s1 = __expf(-1.0f / fmaxf(1.0f - c, 1e-12f));
    float s0 = __expf(-1.0f / fmaxf(c, 1e-12f));
    return s1 / (s1 + s0 + 1e-12f);
}

__device__ __forceinline__ void load_quad(int base, int E,
                                          const float* cut, const float* len,
                                          const int* snd, const int* rcv,
                                          float4& Lv, float4& Cv, int4& Sv, int4& Rv) {
    if (base + 3 < E) {
        Lv = ldcs4((const float4*)(len + base));
        Cv = ldcs4((const float4*)(cut + base));
        Sv = ldcs4i((const int4*)(snd + base));
        Rv = ldcs4i((const int4*)(rcv + base));
    } else {
        float* lp = &Lv.x; float* cp = &Cv.x; int* sp = &Sv.x; int* rp = &Rv.x;
        for (int k = 0; k < 4; k++) {
            int e = base + k;
            lp[k] = (e < E) ? len[e] : 2.0f;   // L >= 1.5 -> w == 0 -> no-op
            cp[k] = (e < E) ? cut[e] : 0.0f;
            sp[k] = (e < E) ? snd[e] : 0;
            rp[k] = (e < E) ? rcv[e] : 0;
        }
    }
}

// Fused: zero output + 16-bit node packing + LUT build (threads < 1536) + params.
__global__ void node_kernel(const float* __restrict__ z,
                            const float* __restrict__ p_raw,
                            const float* __restrict__ d_raw,
                            const float* __restrict__ a1, const float* __restrict__ a2,
                            const float* __restrict__ a3, const float* __restrict__ a4,
                            const float* __restrict__ c1, const float* __restrict__ c2,
                            const float* __restrict__ c3, const float* __restrict__ c4,
                            float* __restrict__ out, int n, int n_out) {
    int i = blockIdx.x * blockDim.x + threadIdx.x;

    if (i < LUT_TOTAL) {
        float A1 = softplus_f(a1[0]), A2 = softplus_f(a2[0]);
        float A3 = softplus_f(a3[0]), A4 = softplus_f(a4[0]);
        float C1 = softplus_f(c1[0]), C2 = softplus_f(c2[0]);
        float C3 = softplus_f(c3[0]), C4 = softplus_f(c4[0]);
        float s = 1.0f / (C1 + C2 + C3 + C4);
        C1 *= s; C2 *= s; C3 *= s; C4 *= s;
        if (i < YLUT_N) {
            float t0 = (float)i       * (YLUT_TMAX / YLUT_N);
            float t1 = (float)(i + 1) * (YLUT_TMAX / YLUT_N);
            float v0 = C1 * __expf(-A1 * t0) + C2 * __expf(-A2 * t0)
                     + C3 * __expf(-A3 * t0) + C4 * __expf(-A4 * t0);
            float v1 = C1 * __expf(-A1 * t1) + C2 * __expf(-A2 * t1)
                     + C3 * __expf(-A3 * t1) + C4 * __expf(-A4 * t1);
            g_lut[i] = make_float2(v0, v1 - v0);
        } else {
            int j = i - YLUT_N;
            float L0 = 0.5f + (float)j       * (1.0f / GLUT_N);
            float L1 = 0.5f + (float)(j + 1) * (1.0f / GLUT_N);
            float v0 = switch_w(L0) / fmaxf(L0, 1e-6f);
            float v1 = switch_w(L1) / fmaxf(L1, 1e-6f);
            g_lut[i] = make_float2(v0, v1 - v0);
        }
    }
    if (i == 0) {
        float P = softplus_f(p_raw[0]);
        float D = softplus_f(d_raw[0]);
        g_par[0] = P;
        g_par[1] = D * ex2f(-11.0f * P);   // z^p*d = DS * 2^(p*lg2(qz)), qz = z*2^11
    }
    if (i < n_out) out[i] = 0.0f;
    if (i < n) {
        unsigned q = __float2uint_rn(z[i] * ZSCALE);
        g_ztab[i] = (uint16_t)(q > 65535u ? 65535u : q);
    }
}

template<bool FITS>
__global__ void __launch_bounds__(NTHREADS, 1)
edge_kernel(const float* __restrict__ cut, const float* __restrict__ len,
            const int* __restrict__ snd, const int* __restrict__ rcv,
            float* __restrict__ out, int E, int tn, int zb) {
    extern __shared__ __align__(16) char sm[];
    uint16_t* s_z = (uint16_t*)sm;
    float2*   s_y = (float2*)(sm + zb);
    float2*   s_g = s_y + YLUT_N;

    // Stage: node table (zb bytes) + LUTs (12288B), uint4-vectorized.
    {
        uint4* dst = (uint4*)sm;
        const uint4* src = (const uint4*)g_ztab;
        int nv = zb >> 4;
        for (int i = threadIdx.x; i < nv; i += NTHREADS) dst[i] = src[i];
        uint4* dl = (uint4*)(sm + zb);
        const uint4* sl = (const uint4*)g_lut;
        for (int i = threadIdx.x; i < (LUT_BYTES >> 4); i += NTHREADS) dl[i] = sl[i];
    }
    __syncthreads();

    const float P  = g_par[0], DS = g_par[1];

    const int nq = (E + 3) >> 2;
    const int stride = gridDim.x * NTHREADS;
    int q = blockIdx.x * NTHREADS + threadIdx.x;
    if (q >= nq) return;

    // Software pipeline: next quad's streaming loads issued before this quad's
    // math, hiding the ~600cyc DRAM latency.
    float4 Lv, Cv; int4 Sv, Rv;
    load_quad(q << 2, E, cut, len, snd, rcv, Lv, Cv, Sv, Rv);

    while (true) {
        int qn = q + stride;
        bool have_next = qn < nq;
        float4 Ln, Cn; int4 Sn, Rn;
        if (have_next) load_quad(qn << 2, E, cut, len, snd, rcv, Ln, Cn, Sn, Rn);

        const float* lp = &Lv.x; const float* cp = &Cv.x;
        const int* sp = &Sv.x; const int* rp = &Rv.x;

        // Fused gather+math per edge: LDS latency (29cyc) is cheap, and fusing
        // keeps live registers minimal so 1024 threads fit 64 regs.
#pragma unroll
        for (int k = 0; k < 4; k++) {
            int s = sp[k], r = rp[k];
            float qs, qr;
            if (FITS) {
                qs = (float)(unsigned)s_z[s];
                qr = (float)(unsigned)s_z[r];
            } else {
                qs = (float)((s < tn) ? (unsigned)s_z[s] : (unsigned)g_ztab[s]);
                qr = (float)((r < tn) ? (unsigned)s_z[r] : (unsigned)g_ztab[r]);
            }

            float L = lp[k];

            // g = w(L)/L via LUT over [0.5, 1.5)
            float fg = (L - 0.5f) * (float)GLUT_N;
            fg = fminf(fmaxf(fg, 0.0f), (float)(GLUT_N - 1));
            int ig = (int)fg; float rg = fg - (float)ig;
            float2 G = s_g[ig];
            float g = fmaf(G.y, rg, G.x);

            // t = L * DS * (2^(P*lg2 qs) + 2^(P*lg2 qr))
            float zps = ex2f(P * lg2f(qs));
            float zpr = ex2f(P * lg2f(qr));
            float t = L * DS * (zps + zpr);

            // y(t) via LUT over [0, 16]
            float ft = t * ((float)YLUT_N / YLUT_TMAX);
            ft = fminf(fmaxf(ft, 0.0f), (float)(YLUT_N - 1));
            int it = (int)ft; float rt = ft - (float)it;
            float2 Y = s_y[it];
            float y = fmaf(Y.y, rt, Y.x);

            float val = (KE_HALF / (ZSCALE * ZSCALE)) * cp[k] * (qs * qr) * g * y;

            if (L < 1.5f) atomicAdd(out + r, val);
        }

        if (!have_next) break;
        q = qn;
        Lv = Ln; Cv = Cn; Sv = Sn; Rv = Rn;
    }
}

extern "C" void kernel_launch(void* const* d_in, const int* in_sizes, int n_in,
                              void* d_out, int out_size) {
    const float* z   = (const float*)d_in[0];
    const float* cut = (const float*)d_in[1];
    const int*   snd = (const int*)  d_in[2];
    const int*   rcv = (const int*)  d_in[3];
    const float* len = (const float*)d_in[4];

    int pb = n_in - 10;
    const float* a1 = (const float*)d_in[pb + 0];
    const float* a2 = (const float*)d_in[pb + 1];
    const float* a3 = (const float*)d_in[pb + 2];
    const float* a4 = (const float*)d_in[pb + 3];
    const float* c1 = (const float*)d_in[pb + 4];
    const float* c2 = (const float*)d_in[pb + 5];
    const float* c3 = (const float*)d_in[pb + 6];
    const float* c4 = (const float*)d_in[pb + 7];
    const float* pr = (const float*)d_in[pb + 8];
    const float* dr = (const float*)d_in[pb + 9];

    int N = in_sizes[0];
    int E = in_sizes[2];
    if (N > MAX_NODES) N = MAX_NODES;

    float* out = (float*)d_out;

    int cover = (N > out_size) ? N : out_size;
    node_kernel<<<(cover + 255) / 256, 256>>>(z, pr, dr, a1, a2, a3, a4,
                                              c1, c2, c3, c4, out, N, out_size);

    int tn = (N < SMEM_CAP_NODES) ? N : SMEM_CAP_NODES;
    int zb = (tn * 2 + 15) & ~15;          // staged table bytes, 16B-aligned
    int smem = zb + LUT_BYTES;

    static int nsm = 0;
    if (nsm == 0) {
        cudaDeviceGetAttribute(&nsm, cudaDevAttrMultiProcessorCount, 0);
        if (nsm <= 0) nsm = 148;
        cudaFuncSetAttribute(edge_kernel<true>,
                             cudaFuncAttributeMaxDynamicSharedMemorySize,
                             SMEM_CAP_NODES * 2 + 16 + LUT_BYTES);
        cudaFuncSetAttribute(edge_kernel<false>,
                             cudaFuncAttributeMaxDynamicSharedMemorySize,
                             SMEM_CAP_NODES * 2 + 16 + LUT_BYTES);
    }
    if (N <= SMEM_CAP_NODES)
        edge_kernel<true><<<nsm, NTHREADS, smem>>>(cut, len, snd, rcv, out, E, tn, zb);
    else
        edge_kernel<false><<<nsm, NTHREADS, smem>>>(cut, len, snd, rcv, out, E, tn, zb);
}

// round 15
// speedup vs baseline: 1.2355x; 1.0515x over previous
#include <cuda_runtime.h>
#include <stdint.h>

#define KE_HALF 7.199822675975274f   /* KE/2 */
#define LOG2E   1.4426950408889634f
#define MAX_NODES 131072
#define ZSCALE   2048.0f
#define YLUT_N   1024
#define YLUT_TMAX 16.0f
#define GLUT_N   512                 /* over L in [0.5, 1.5) */
#define LUT_TOTAL (YLUT_N + GLUT_N)
#define LUT_BYTES (LUT_TOTAL * 8)    /* 12288 */
#define SMEM_CAP_NODES 104000        /* table cap: 208000B + 12288B LUT */
#define NTHREADS 768

// 2B per node: qz = round(z * 2048).
__device__ uint16_t g_ztab[MAX_NODES];
// Prebuilt LUTs: [0,1024) y(t) over [0,16]; [1024,1536) w(L)/L over [0.5,1.5).
__device__ float2   g_lut[LUT_TOTAL];
__device__ float    g_par[4];        // [0]=p, [1]=d*2^(-11p)

__device__ __forceinline__ float softplus_f(float x) {
    return fmaxf(x, 0.0f) + log1pf(__expf(-fabsf(x)));
}
__device__ __forceinline__ float ex2f(float x) {
    float y; asm("ex2.approx.ftz.f32 %0, %1;" : "=f"(y) : "f"(x)); return y;
}
__device__ __forceinline__ float lg2f(float x) {
    float y; asm("lg2.approx.ftz.f32 %0, %1;" : "=f"(y) : "f"(x)); return y;
}

__device__ __forceinline__ float4 ldcs4(const float4* p) {
    float4 v;
    asm("ld.global.cs.v4.f32 {%0,%1,%2,%3}, [%4];"
        : "=f"(v.x), "=f"(v.y), "=f"(v.z), "=f"(v.w) : "l"(p));
    return v;
}
__device__ __forceinline__ int4 ldcs4i(const int4* p) {
    int4 v;
    asm("ld.global.cs.v4.b32 {%0,%1,%2,%3}, [%4];"
        : "=r"(v.x), "=r"(v.y), "=r"(v.z), "=r"(v.w) : "l"(p));
    return v;
}

__device__ __forceinline__ float switch_w(float L) {
    float c = L * (1.0f / 1.5f);
    if (c >= 1.0f) return 0.0f;
    float s1 = __expf(-1.0f / fmaxf(1.0f - c, 1e-12f));
    float s0 = __expf(-1.0f / fmaxf(c, 1e-12f));
    return s1 / (s1 + s0 + 1e-12f);
}

__device__ __forceinline__ void load_quad(int base, int E,
                                          const float* cut, const float* len,
                                          const int* snd, const int* rcv,
                                          float4& Lv, float4& Cv, int4& Sv, int4& Rv) {
    if (base + 3 < E) {
        Lv = ldcs4((const float4*)(len + base));
        Cv = ldcs4((const float4*)(cut + base));
        Sv = ldcs4i((const int4*)(snd + base));
        Rv = ldcs4i((const int4*)(rcv + base));
    } else {
        float* lp = &Lv.x; float* cp = &Cv.x; int* sp = &Sv.x; int* rp = &Rv.x;
        for (int k = 0; k < 4; k++) {
            int e = base + k;
            lp[k] = (e < E) ? len[e] : 2.0f;   // L >= 1.5 -> w == 0 -> no-op
            cp[k] = (e < E) ? cut[e] : 0.0f;
            sp[k] = (e < E) ? snd[e] : 0;
            rp[k] = (e < E) ? rcv[e] : 0;
        }
    }
}

// Fused: zero output + 16-bit node packing + LUT build (threads < 1536) + params.
__global__ void node_kernel(const float* __restrict__ z,
                            const float* __restrict__ p_raw,
                            const float* __restrict__ d_raw,
                            const float* __restrict__ a1, const float* __restrict__ a2,
                            const float* __restrict__ a3, const float* __restrict__ a4,
                            const float* __restrict__ c1, const float* __restrict__ c2,
                            const float* __restrict__ c3, const float* __restrict__ c4,
                            float* __restrict__ out, int n, int n_out) {
    int i = blockIdx.x * blockDim.x + threadIdx.x;

    if (i < LUT_TOTAL) {
        float A1 = softplus_f(a1[0]), A2 = softplus_f(a2[0]);
        float A3 = softplus_f(a3[0]), A4 = softplus_f(a4[0]);
        float C1 = softplus_f(c1[0]), C2 = softplus_f(c2[0]);
        float C3 = softplus_f(c3[0]), C4 = softplus_f(c4[0]);
        float s = 1.0f / (C1 + C2 + C3 + C4);
        C1 *= s; C2 *= s; C3 *= s; C4 *= s;
        if (i < YLUT_N) {
            float t0 = (float)i       * (YLUT_TMAX / YLUT_N);
            float t1 = (float)(i + 1) * (YLUT_TMAX / YLUT_N);
            float v0 = C1 * __expf(-A1 * t0) + C2 * __expf(-A2 * t0)
                     + C3 * __expf(-A3 * t0) + C4 * __expf(-A4 * t0);
            float v1 = C1 * __expf(-A1 * t1) + C2 * __expf(-A2 * t1)
                     + C3 * __expf(-A3 * t1) + C4 * __expf(-A4 * t1);
            g_lut[i] = make_float2(v0, v1 - v0);
        } else {
            int j = i - YLUT_N;
            float L0 = 0.5f + (float)j       * (1.0f / GLUT_N);
            float L1 = 0.5f + (float)(j + 1) * (1.0f / GLUT_N);
            float v0 = switch_w(L0) / fmaxf(L0, 1e-6f);
            float v1 = switch_w(L1) / fmaxf(L1, 1e-6f);
            g_lut[i] = make_float2(v0, v1 - v0);
        }
    }
    if (i == 0) {
        float P = softplus_f(p_raw[0]);
        float D = softplus_f(d_raw[0]);
        g_par[0] = P;
        g_par[1] = D * ex2f(-11.0f * P);   // z^p*d = DS * 2^(p*lg2(qz)), qz = z*2^11
    }
    if (i < n_out) out[i] = 0.0f;
    if (i < n) {
        unsigned q = __float2uint_rn(z[i] * ZSCALE);
        g_ztab[i] = (uint16_t)(q > 65535u ? 65535u : q);
    }
}

template<bool FITS>
__global__ void __launch_bounds__(NTHREADS, 1)
edge_kernel(const float* __restrict__ cut, const float* __restrict__ len,
            const int* __restrict__ snd, const int* __restrict__ rcv,
            float* __restrict__ out, int E, int tn, int zb) {
    extern __shared__ __align__(16) char sm[];
    uint16_t* s_z = (uint16_t*)sm;
    float2*   s_y = (float2*)(sm + zb);
    float2*   s_g = s_y + YLUT_N;

    // Stage: node table (zb bytes) + LUTs (12288B), uint4-vectorized.
    {
        uint4* dst = (uint4*)sm;
        const uint4* src = (const uint4*)g_ztab;
        int nv = zb >> 4;
        for (int i = threadIdx.x; i < nv; i += NTHREADS) dst[i] = src[i];
        uint4* dl = (uint4*)(sm + zb);
        const uint4* sl = (const uint4*)g_lut;
        for (int i = threadIdx.x; i < (LUT_BYTES >> 4); i += NTHREADS) dl[i] = sl[i];
    }
    __syncthreads();

    const float P  = g_par[0], DS = g_par[1];

    const int nq = (E + 3) >> 2;
    const int stride = gridDim.x * NTHREADS;

    int q0 = blockIdx.x * NTHREADS + threadIdx.x;
    if (q0 >= nq) return;

    // ── 2-deep software pipeline: quads q0 (A), q0+s (B) in flight; each
    //    iteration issues q0+2s (C) before processing A. ~192 in-flight
    //    streaming loads per SM — covers the full DRAM latency.
    float4 LA, CA; int4 SA, RA;
    load_quad(q0 << 2, E, cut, len, snd, rcv, LA, CA, SA, RA);

    int q1 = q0 + stride;
    bool h1 = q1 < nq;
    float4 LB, CB; int4 SB, RB;
    if (h1) load_quad(q1 << 2, E, cut, len, snd, rcv, LB, CB, SB, RB);

    while (true) {
        int q2 = q1 + stride;
        bool h2 = h1 && (q2 < nq);
        float4 LC, CC; int4 SC, RC;
        if (h2) load_quad(q2 << 2, E, cut, len, snd, rcv, LC, CC, SC, RC);

        const float* lp = &LA.x; const float* cp = &CA.x;
        const int* sp = &SA.x; const int* rp = &RA.x;

        // Fused gather+LUT math per edge; only the RED is predicated.
#pragma unroll
        for (int k = 0; k < 4; k++) {
            int s = sp[k], r = rp[k];
            float qs, qr;
            if (FITS) {
                qs = (float)(unsigned)s_z[s];
                qr = (float)(unsigned)s_z[r];
            } else {
                qs = (float)((s < tn) ? (unsigned)s_z[s] : (unsigned)g_ztab[s]);
                qr = (float)((r < tn) ? (unsigned)s_z[r] : (unsigned)g_ztab[r]);
            }

            float L = lp[k];

            // g = w(L)/L via LUT over [0.5, 1.5)
            float fg = (L - 0.5f) * (float)GLUT_N;
            fg = fminf(fmaxf(fg, 0.0f), (float)(GLUT_N - 1));
            int ig = (int)fg; float rg = fg - (float)ig;
            float2 G = s_g[ig];
            float g = fmaf(G.y, rg, G.x);

            // t = L * DS * (2^(P*lg2 qs) + 2^(P*lg2 qr))
            float zps = ex2f(P * lg2f(qs));
            float zpr = ex2f(P * lg2f(qr));
            float t = L * DS * (zps + zpr);

            // y(t) via LUT over [0, 16]
            float ft = t * ((float)YLUT_N / YLUT_TMAX);
            ft = fminf(fmaxf(ft, 0.0f), (float)(YLUT_N - 1));
            int it = (int)ft; float rt = ft - (float)it;
            float2 Y = s_y[it];
            float y = fmaf(Y.y, rt, Y.x);

            float val = (KE_HALF / (ZSCALE * ZSCALE)) * cp[k] * (qs * qr) * g * y;

            if (L < 1.5f) atomicAdd(out + r, val);
        }

        if (!h1) break;
        // rotate pipeline
        LA = LB; CA = CB; SA = SB; RA = RB;
        LB = LC; CB = CC; SB = SC; RB = RC;
        q1 = q2; h1 = h2;
    }
}

extern "C" void kernel_launch(void* const* d_in, const int* in_sizes, int n_in,
                              void* d_out, int out_size) {
    const float* z   = (const float*)d_in[0];
    const float* cut = (const float*)d_in[1];
    const int*   snd = (const int*)  d_in[2];
    const int*   rcv = (const int*)  d_in[3];
    const float* len = (const float*)d_in[4];

    int pb = n_in - 10;
    const float* a1 = (const float*)d_in[pb + 0];
    const float* a2 = (const float*)d_in[pb + 1];
    const float* a3 = (const float*)d_in[pb + 2];
    const float* a4 = (const float*)d_in[pb + 3];
    const float* c1 = (const float*)d_in[pb + 4];
    const float* c2 = (const float*)d_in[pb + 5];
    const float* c3 = (const float*)d_in[pb + 6];
    const float* c4 = (const float*)d_in[pb + 7];
    const float* pr = (const float*)d_in[pb + 8];
    const float* dr = (const float*)d_in[pb + 9];

    int N = in_sizes[0];
    int E = in_sizes[2];
    if (N > MAX_NODES) N = MAX_NODES;

    float* out = (float*)d_out;

    int cover = (N > out_size) ? N : out_size;
    node_kernel<<<(cover + 255) / 256, 256>>>(z, pr, dr, a1, a2, a3, a4,
                                              c1, c2, c3, c4, out, N, out_size);

    int tn = (N < SMEM_CAP_NODES) ? N : SMEM_CAP_NODES;
    int zb = (tn * 2 + 15) & ~15;          // staged table bytes, 16B-aligned
    int smem = zb + LUT_BYTES;

    static int nsm = 0;
    if (nsm == 0) {
        cudaDeviceGetAttribute(&nsm, cudaDevAttrMultiProcessorCount, 0);
        if (nsm <= 0) nsm = 148;
        cudaFuncSetAttribute(edge_kernel<true>,
                             cudaFuncAttributeMaxDynamicSharedMemorySize,
                             SMEM_CAP_NODES * 2 + 16 + LUT_BYTES);
        cudaFuncSetAttribute(edge_kernel<false>,
                             cudaFuncAttributeMaxDynamicSharedMemorySize,
                             SMEM_CAP_NODES * 2 + 16 + LUT_BYTES);
    }
    if (N <= SMEM_CAP_NODES)
        edge_kernel<true><<<nsm, NTHREADS, smem>>>(cut, len, snd, rcv, out, E, tn, zb);
    else
        edge_kernel<false><<<nsm, NTHREADS, smem>>>(cut, len, snd, rcv, out, E, tn, zb);
}

// round 16
// speedup vs baseline: 1.2366x; 1.0010x over previous
#include <cuda_runtime.h>
#include <stdint.h>

#define KE_HALF 7.199822675975274f   /* KE/2 */
#define LOG2E   1.4426950408889634f
#define MAX_NODES 131072
#define ZSCALE   2048.0f
#define SMEM_CAP_NODES 110000        /* 2B each -> 220KB cap */
#define NTHREADS 768

// 2B per node: qz = round(z * 2048).
__device__ uint16_t g_ztab[MAX_NODES];
__device__ float    g_par[12];  // [0..3]=-a_k*log2e, [4..7]=c_k norm, [8]=p, [9]=d*2^(-11p)

__device__ __forceinline__ float softplus_f(float x) {
    return fmaxf(x, 0.0f) + log1pf(__expf(-fabsf(x)));
}
__device__ __forceinline__ float ex2f(float x) {
    float y; asm("ex2.approx.ftz.f32 %0, %1;" : "=f"(y) : "f"(x)); return y;
}
__device__ __forceinline__ float lg2f(float x) {
    float y; asm("lg2.approx.ftz.f32 %0, %1;" : "=f"(y) : "f"(x)); return y;
}

__device__ __forceinline__ float4 ldcs4(const float4* p) {
    float4 v;
    asm("ld.global.cs.v4.f32 {%0,%1,%2,%3}, [%4];"
        : "=f"(v.x), "=f"(v.y), "=f"(v.z), "=f"(v.w) : "l"(p));
    return v;
}
__device__ __forceinline__ int4 ldcs4i(const int4* p) {
    int4 v;
    asm("ld.global.cs.v4.b32 {%0,%1,%2,%3}, [%4];"
        : "=r"(v.x), "=r"(v.y), "=r"(v.z), "=r"(v.w) : "l"(p));
    return v;
}

__device__ __forceinline__ void load_quad(int base, int E,
                                          const float* cut, const float* len,
                                          const int* snd, const int* rcv,
                                          float4& Lv, float4& Cv, int4& Sv, int4& Rv) {
    if (base + 3 < E) {
        Lv = ldcs4((const float4*)(len + base));
        Cv = ldcs4((const float4*)(cut + base));
        Sv = ldcs4i((const int4*)(snd + base));
        Rv = ldcs4i((const int4*)(rcv + base));
    } else {
        float* lp = &Lv.x; float* cp = &Cv.x; int* sp = &Sv.x; int* rp = &Rv.x;
        for (int k = 0; k < 4; k++) {
            int e = base + k;
            lp[k] = (e < E) ? len[e] : 2.0f;   // L >= 1.5 -> w == 0 -> no-op
            cp[k] = (e < E) ? cut[e] : 0.0f;
            sp[k] = (e < E) ? snd[e] : 0;
            rp[k] = (e < E) ? rcv[e] : 0;
        }
    }
}

// Fused: zero output + 16-bit node quantization + (thread 0) param derivation.
__global__ void node_kernel(const float* __restrict__ z,
                            const float* __restrict__ p_raw,
                            const float* __restrict__ d_raw,
                            const float* __restrict__ a1, const float* __restrict__ a2,
                            const float* __restrict__ a3, const float* __restrict__ a4,
                            const float* __restrict__ c1, const float* __restrict__ c2,
                            const float* __restrict__ c3, const float* __restrict__ c4,
                            float* __restrict__ out, int n, int n_out) {
    int i = blockIdx.x * blockDim.x + threadIdx.x;
    if (i == 0) {
        float A1 = softplus_f(a1[0]), A2 = softplus_f(a2[0]);
        float A3 = softplus_f(a3[0]), A4 = softplus_f(a4[0]);
        float C1 = softplus_f(c1[0]), C2 = softplus_f(c2[0]);
        float C3 = softplus_f(c3[0]), C4 = softplus_f(c4[0]);
        float s = 1.0f / (C1 + C2 + C3 + C4);
        float P = softplus_f(p_raw[0]);
        float D = softplus_f(d_raw[0]);
        g_par[0] = -A1 * LOG2E; g_par[1] = -A2 * LOG2E;
        g_par[2] = -A3 * LOG2E; g_par[3] = -A4 * LOG2E;
        g_par[4] = C1 * s; g_par[5] = C2 * s; g_par[6] = C3 * s; g_par[7] = C4 * s;
        g_par[8] = P;
        g_par[9] = D * ex2f(-11.0f * P);   // z^p*d = DS * 2^(p*lg2(qz)), qz = z*2^11
    }
    if (i < n_out) out[i] = 0.0f;
    if (i < n) {
        unsigned q = __float2uint_rn(z[i] * ZSCALE);
        g_ztab[i] = (uint16_t)(q > 65535u ? 65535u : q);
    }
}

template<bool FITS>
__global__ void __launch_bounds__(NTHREADS, 1)
edge_kernel(const float* __restrict__ cut, const float* __restrict__ len,
            const int* __restrict__ snd, const int* __restrict__ rcv,
            float* __restrict__ out, int E, int tn) {
    extern __shared__ __align__(16) uint16_t s_z[];

    // Stage the node table into smem (uint4-vectorized).
    {
        uint4* dst = (uint4*)s_z;
        const uint4* src = (const uint4*)g_ztab;
        int nv = (tn * 2 + 15) >> 4;
        for (int i = threadIdx.x; i < nv; i += NTHREADS) dst[i] = src[i];
    }
    __syncthreads();

    const float b1 = g_par[0], b2 = g_par[1], b3 = g_par[2], b4 = g_par[3];
    const float c1 = g_par[4], c2 = g_par[5], c3 = g_par[6], c4 = g_par[7];
    const float P  = g_par[8], DS = g_par[9];

    const int nq = (E + 3) >> 2;
    const int stride = gridDim.x * NTHREADS;

    int q0 = blockIdx.x * NTHREADS + threadIdx.x;
    if (q0 >= nq) return;

    // 2-deep software pipeline over the streaming loads.
    float4 LA, CA; int4 SA, RA;
    load_quad(q0 << 2, E, cut, len, snd, rcv, LA, CA, SA, RA);

    int q1 = q0 + stride;
    bool h1 = q1 < nq;
    float4 LB, CB; int4 SB, RB;
    if (h1) load_quad(q1 << 2, E, cut, len, snd, rcv, LB, CB, SB, RB);

    while (true) {
        int q2 = q1 + stride;
        bool h2 = h1 && (q2 < nq);
        float4 LC, CC; int4 SC, RC;
        if (h2) load_quad(q2 << 2, E, cut, len, snd, rcv, LC, CC, SC, RC);

        const float* lp = &LA.x; const float* cp = &CA.x;
        const int* sp = &SA.x; const int* rp = &RA.x;

        // Fused gather + MUFU math per edge; only the RED is predicated.
        // (LUT-free: all transcendental work rides the MUFU pipe, leaving
        //  the LSU/smem pipe for streaming + gathers + atomics.)
#pragma unroll
        for (int k = 0; k < 4; k++) {
            int s = sp[k], r = rp[k];
            float qs, qr;
            if (FITS) {
                qs = (float)(unsigned)s_z[s];
                qr = (float)(unsigned)s_z[r];
            } else {
                qs = (float)((s < tn) ? (unsigned)s_z[s] : (unsigned)g_ztab[s]);
                qr = (float)((r < tn) ? (unsigned)s_z[r] : (unsigned)g_ztab[r]);
            }

            float L = lp[k];
            float cc = L * (1.0f / 1.5f);

            // w*x*0.5 = KE_HALF*cut*zi*zj / ((1 + 2^fl) * L)
            float om = 1.0f - cc;
            float fl = __fdividef((cc + cc - 1.0f) * LOG2E, cc * om);
            float ef = ex2f(fl);
            float D  = (1.0f + ef) * fmaxf(L, 1e-6f);

            // z^p*d = DS * 2^(P * lg2(qz))
            float zps = ex2f(P * lg2f(qs));
            float zpr = ex2f(P * lg2f(qr));
            float t   = L * DS * (zps + zpr);            // rzd

            float y = c1 * ex2f(b1 * t) + c2 * ex2f(b2 * t)
                    + c3 * ex2f(b3 * t) + c4 * ex2f(b4 * t);

            float num = (KE_HALF / (ZSCALE * ZSCALE)) * cp[k] * (qs * qr);
            float val = __fdividef(num * y, D);

            if (L < 1.5f) atomicAdd(out + r, val);
        }

        if (!h1) break;
        LA = LB; CA = CB; SA = SB; RA = RB;
        LB = LC; CB = CC; SB = SC; RB = RC;
        q1 = q2; h1 = h2;
    }
}

extern "C" void kernel_launch(void* const* d_in, const int* in_sizes, int n_in,
                              void* d_out, int out_size) {
    const float* z   = (const float*)d_in[0];
    const float* cut = (const float*)d_in[1];
    const int*   snd = (const int*)  d_in[2];
    const int*   rcv = (const int*)  d_in[3];
    const float* len = (const float*)d_in[4];

    int pb = n_in - 10;
    const float* a1 = (const float*)d_in[pb + 0];
    const float* a2 = (const float*)d_in[pb + 1];
    const float* a3 = (const float*)d_in[pb + 2];
    const float* a4 = (const float*)d_in[pb + 3];
    const float* c1 = (const float*)d_in[pb + 4];
    const float* c2 = (const float*)d_in[pb + 5];
    const float* c3 = (const float*)d_in[pb + 6];
    const float* c4 = (const float*)d_in[pb + 7];
    const float* pr = (const float*)d_in[pb + 8];
    const float* dr = (const float*)d_in[pb + 9];

    int N = in_sizes[0];
    int E = in_sizes[2];
    if (N > MAX_NODES) N = MAX_NODES;

    float* out = (float*)d_out;

    int cover = (N > out_size) ? N : out_size;
    node_kernel<<<(cover + 255) / 256, 256>>>(z, pr, dr, a1, a2, a3, a4,
                                              c1, c2, c3, c4, out, N, out_size);

    int tn = (N < SMEM_CAP_NODES) ? N : SMEM_CAP_NODES;
    int smem = (tn * 2 + 15) & ~15;

    static int nsm = 0;
    if (nsm == 0) {
        cudaDeviceGetAttribute(&nsm, cudaDevAttrMultiProcessorCount, 0);
        if (nsm <= 0) nsm = 148;
        cudaFuncSetAttribute(edge_kernel<true>,
                             cudaFuncAttributeMaxDynamicSharedMemorySize,
                             SMEM_CAP_NODES * 2 + 16);
        cudaFuncSetAttribute(edge_kernel<false>,
                             cudaFuncAttributeMaxDynamicSharedMemorySize,
                             SMEM_CAP_NODES * 2 + 16);
    }
    if (N <= SMEM_CAP_NODES)
        edge_kernel<true><<<nsm, NTHREADS, smem>>>(cut, len, snd, rcv, out, E, tn);
    else
        edge_kernel<false><<<nsm, NTHREADS, smem>>>(cut, len, snd, rcv, out, E, tn);
}

// round 17
// speedup vs baseline: 1.2656x; 1.0234x over previous
#include <cuda_runtime.h>
#include <stdint.h>

#define KE_HALF 7.199822675975274f   /* KE/2 */
#define LOG2E   1.4426950408889634f
#define MAX_NODES 131072
#define ZSCALE   2048.0f
#define SMEM_CAP_NODES 110000        /* 2B each -> 220KB cap */
#define NTHREADS 1024

// 2B per node: qz = round(z * 2048).
__device__ uint16_t g_ztab[MAX_NODES];
__device__ float    g_par[12];  // [0..3]=-a_k*log2e, [4..7]=c_k norm, [8]=p, [9]=d*2^(-11p)

__device__ __forceinline__ float softplus_f(float x) {
    return fmaxf(x, 0.0f) + log1pf(__expf(-fabsf(x)));
}
__device__ __forceinline__ float ex2f(float x) {
    float y; asm("ex2.approx.ftz.f32 %0, %1;" : "=f"(y) : "f"(x)); return y;
}
__device__ __forceinline__ float lg2f(float x) {
    float y; asm("lg2.approx.ftz.f32 %0, %1;" : "=f"(y) : "f"(x)); return y;
}

__device__ __forceinline__ float4 ldcs4(const float4* p) {
    float4 v;
    asm("ld.global.cs.v4.f32 {%0,%1,%2,%3}, [%4];"
        : "=f"(v.x), "=f"(v.y), "=f"(v.z), "=f"(v.w) : "l"(p));
    return v;
}
__device__ __forceinline__ int4 ldcs4i(const int4* p) {
    int4 v;
    asm("ld.global.cs.v4.b32 {%0,%1,%2,%3}, [%4];"
        : "=r"(v.x), "=r"(v.y), "=r"(v.z), "=r"(v.w) : "l"(p));
    return v;
}

__device__ __forceinline__ void load_quad(int base, int E,
                                          const float* cut, const float* len,
                                          const int* snd, const int* rcv,
                                          float4& Lv, float4& Cv, int4& Sv, int4& Rv) {
    if (base + 3 < E) {
        Lv = ldcs4((const float4*)(len + base));
        Cv = ldcs4((const float4*)(cut + base));
        Sv = ldcs4i((const int4*)(snd + base));
        Rv = ldcs4i((const int4*)(rcv + base));
    } else {
        float* lp = &Lv.x; float* cp = &Cv.x; int* sp = &Sv.x; int* rp = &Rv.x;
        for (int k = 0; k < 4; k++) {
            int e = base + k;
            lp[k] = (e < E) ? len[e] : 2.0f;   // L >= 1.5 -> w == 0 -> no-op
            cp[k] = (e < E) ? cut[e] : 0.0f;
            sp[k] = (e < E) ? snd[e] : 0;
            rp[k] = (e < E) ? rcv[e] : 0;
        }
    }
}

// Fused: zero output + 16-bit node quantization + (thread 0) param derivation.
__global__ void node_kernel(const float* __restrict__ z,
                            const float* __restrict__ p_raw,
                            const float* __restrict__ d_raw,
                            const float* __restrict__ a1, const float* __restrict__ a2,
                            const float* __restrict__ a3, const float* __restrict__ a4,
                            const float* __restrict__ c1, const float* __restrict__ c2,
                            const float* __restrict__ c3, const float* __restrict__ c4,
                            float* __restrict__ out, int n, int n_out) {
    int i = blockIdx.x * blockDim.x + threadIdx.x;
    if (i == 0) {
        float A1 = softplus_f(a1[0]), A2 = softplus_f(a2[0]);
        float A3 = softplus_f(a3[0]), A4 = softplus_f(a4[0]);
        float C1 = softplus_f(c1[0]), C2 = softplus_f(c2[0]);
        float C3 = softplus_f(c3[0]), C4 = softplus_f(c4[0]);
        float s = 1.0f / (C1 + C2 + C3 + C4);
        float P = softplus_f(p_raw[0]);
        float D = softplus_f(d_raw[0]);
        g_par[0] = -A1 * LOG2E; g_par[1] = -A2 * LOG2E;
        g_par[2] = -A3 * LOG2E; g_par[3] = -A4 * LOG2E;
        g_par[4] = C1 * s; g_par[5] = C2 * s; g_par[6] = C3 * s; g_par[7] = C4 * s;
        g_par[8] = P;
        g_par[9] = D * ex2f(-11.0f * P);   // z^p*d = DS * 2^(p*lg2(qz)), qz = z*2^11
    }
    if (i < n_out) out[i] = 0.0f;
    if (i < n) {
        unsigned q = __float2uint_rn(z[i] * ZSCALE);
        g_ztab[i] = (uint16_t)(q > 65535u ? 65535u : q);
    }
}

template<bool FITS>
__global__ void __launch_bounds__(NTHREADS, 1)
edge_kernel(const float* __restrict__ cut, const float* __restrict__ len,
            const int* __restrict__ snd, const int* __restrict__ rcv,
            float* __restrict__ out, int E, int tn) {
    extern __shared__ __align__(16) uint16_t s_z[];

    // Stage the node table into smem (uint4-vectorized).
    {
        uint4* dst = (uint4*)s_z;
        const uint4* src = (const uint4*)g_ztab;
        int nv = (tn * 2 + 15) >> 4;
        for (int i = threadIdx.x; i < nv; i += NTHREADS) dst[i] = src[i];
    }
    __syncthreads();

    const float b1 = g_par[0], b2 = g_par[1], b3 = g_par[2], b4 = g_par[3];
    const float c1 = g_par[4], c2 = g_par[5], c3 = g_par[6], c4 = g_par[7];
    const float P  = g_par[8], DS = g_par[9];

    const int nq = (E + 3) >> 2;
    const int stride = gridDim.x * NTHREADS;

    int q = blockIdx.x * NTHREADS + threadIdx.x;
    if (q >= nq) return;

    // 1-deep software pipeline (keeps regs <= 64 so 1024 threads fit the
    // regfile -> 32 warps/SM interleaving the LSU streams).
    float4 Lv, Cv; int4 Sv, Rv;
    load_quad(q << 2, E, cut, len, snd, rcv, Lv, Cv, Sv, Rv);

    while (true) {
        int qn = q + stride;
        bool have_next = qn < nq;
        float4 Ln, Cn; int4 Sn, Rn;
        if (have_next) load_quad(qn << 2, E, cut, len, snd, rcv, Ln, Cn, Sn, Rn);

        const float* lp = &Lv.x; const float* cp = &Cv.x;
        const int* sp = &Sv.x; const int* rp = &Rv.x;

        // Fused gather + MUFU math per edge; only the RED is predicated.
#pragma unroll
        for (int k = 0; k < 4; k++) {
            int s = sp[k], r = rp[k];
            float qs, qr;
            if (FITS) {
                qs = (float)(unsigned)s_z[s];
                qr = (float)(unsigned)s_z[r];
            } else {
                qs = (float)((s < tn) ? (unsigned)s_z[s] : (unsigned)g_ztab[s]);
                qr = (float)((r < tn) ? (unsigned)s_z[r] : (unsigned)g_ztab[r]);
            }

            float L = lp[k];
            float cc = L * (1.0f / 1.5f);

            // w*x*0.5 = KE_HALF*cut*zi*zj / ((1 + 2^fl) * L)
            float om = 1.0f - cc;
            float fl = __fdividef((cc + cc - 1.0f) * LOG2E, cc * om);
            float ef = ex2f(fl);
            float D  = (1.0f + ef) * fmaxf(L, 1e-6f);

            // z^p*d = DS * 2^(P * lg2(qz))
            float zps = ex2f(P * lg2f(qs));
            float zpr = ex2f(P * lg2f(qr));
            float t   = L * DS * (zps + zpr);            // rzd

            float y = c1 * ex2f(b1 * t) + c2 * ex2f(b2 * t)
                    + c3 * ex2f(b3 * t) + c4 * ex2f(b4 * t);

            float num = (KE_HALF / (ZSCALE * ZSCALE)) * cp[k] * (qs * qr);
            float val = __fdividef(num * y, D);

            if (L < 1.5f) atomicAdd(out + r, val);
        }

        if (!have_next) break;
        q = qn;
        Lv = Ln; Cv = Cn; Sv = Sn; Rv = Rn;
    }
}

extern "C" void kernel_launch(void* const* d_in, const int* in_sizes, int n_in,
                              void* d_out, int out_size) {
    const float* z   = (const float*)d_in[0];
    const float* cut = (const float*)d_in[1];
    const int*   snd = (const int*)  d_in[2];
    const int*   rcv = (const int*)  d_in[3];
    const float* len = (const float*)d_in[4];

    int pb = n_in - 10;
    const float* a1 = (const float*)d_in[pb + 0];
    const float* a2 = (const float*)d_in[pb + 1];
    const float* a3 = (const float*)d_in[pb + 2];
    const float* a4 = (const float*)d_in[pb + 3];
    const float* c1 = (const float*)d_in[pb + 4];
    const float* c2 = (const float*)d_in[pb + 5];
    const float* c3 = (const float*)d_in[pb + 6];
    const float* c4 = (const float*)d_in[pb + 7];
    const float* pr = (const float*)d_in[pb + 8];
    const float* dr = (const float*)d_in[pb + 9];

    int N = in_sizes[0];
    int E = in_sizes[2];
    if (N > MAX_NODES) N = MAX_NODES;

    float* out = (float*)d_out;

    int cover = (N > out_size) ? N : out_size;
    node_kernel<<<(cover + 255) / 256, 256>>>(z, pr, dr, a1, a2, a3, a4,
                                              c1, c2, c3, c4, out, N, out_size);

    int tn = (N < SMEM_CAP_NODES) ? N : SMEM_CAP_NODES;
    int smem = (tn * 2 + 15) & ~15;

    static int nsm = 0;
    if (nsm == 0) {
        cudaDeviceGetAttribute(&nsm, cudaDevAttrMultiProcessorCount, 0);
        if (nsm <= 0) nsm = 148;
        cudaFuncSetAttribute(edge_kernel<true>,
                             cudaFuncAttributeMaxDynamicSharedMemorySize,
                             SMEM_CAP_NODES * 2 + 16);
        cudaFuncSetAttribute(edge_kernel<false>,
                             cudaFuncAttributeMaxDynamicSharedMemorySize,
                             SMEM_CAP_NODES * 2 + 16);
    }
    if (N <= SMEM_CAP_NODES)
        edge_kernel<true><<<nsm, NTHREADS, smem>>>(cut, len, snd, rcv, out, E, tn);
    else
        edge_kernel<false><<<nsm, NTHREADS, smem>>>(cut, len, snd, rcv, out, E, tn);
}